// round 17
// baseline (speedup 1.0000x reference)
#include <cuda_runtime.h>
#include <math.h>

// ---------------- constants matching the reference ----------------
#define HH 121
#define WW 121
#define NE 225
#define NB 8
#define N_INTERP 200
#define RET_PER_DVA 280.0f
#define XRANGE0 (-15.0f)
#define YRANGE0 (-15.0f)
#define XYSTEP 0.25f
#define XLOWc (-4200.0f)
#define YLOWc (-4200.0f)
#define STEP_Xc (8400.0f/199.0f)
#define STEP_Yc (8400.0f/199.0f)
#define OD_OFF_Xc (15.5f*280.0f)
#define AMP_CUTOFF 0.25f
#define PIc 3.14159265358979323846f
#define TEMP1c (4.0f*PIc)
#define NEG_HALF_LOG2E (-0.7213475204444817f)   // -0.5*log2(e)
#define HALF_LOG2E 0.7213475204444817f
#define LOG2_045 (-1.1520030934450498f)         // log2(0.45)
#define CULL_T 16.0f                   // exp2(-16) ~ 1.5e-5 per dropped term

#define NPIX (HH*WW)
#define TILES_X 8
#define TILES_Y 8

__device__ __forceinline__ float ex2_fast(float x) {
    float r;
    asm("ex2.approx.ftz.f32 %0, %1;" : "=f"(r) : "f"(x));
    return r;
}

// ONE kernel. grid (8, 8, NB) = 512 blocks, block 256 (8 warps), 16x16 tile.
// Phase 1a: cheap cull over all 225 electrodes (one per thread) — cull
//   radius from sy alone (exact lmin = 0.7213/sy), no slopes/theta needed.
// Compaction: block-wide deterministic survivor index list (ascending e),
//   zero-padded by 8 entries so the ILP-2 loop needs no edge handling.
// Phase 1b: full transcendental chain for survivors only.
// Phase 2: balanced ILP-2 survivor loop — warp w takes pairs (s, s+8) for
//   s = w, w+16, ...; two independent 8-row FD chains in flight.
// Phase 3: block-local 8-warp reduction in fixed order -> STG.
__global__ __launch_bounds__(256) void mvg_kernel(
        const float* __restrict__ stim,
        const float* __restrict__ params,
        const float* __restrict__ elec_x,
        const float* __restrict__ elec_y,
        const float* __restrict__ slopes,
        float* __restrict__ out) {
    __shared__ int    cIdx[NE];        // survivor electrode ids (ascending)
    __shared__ float4 cA[NE + 8];      // survivors: cx, cy2, -, bright  (+pad)
    __shared__ float4 cB[NE + 8];      // c00, c01, c11, 2*c11           (+pad)
    __shared__ float  spart[8][256];   // [warp][pixel-in-tile]
    __shared__ int    wcnt[8];
    __shared__ int    s_len;

    int b = blockIdx.z;
    int tid = threadIdx.x;
    int lane = tid & 31, w = tid >> 5;

    // tile center (block-uniform)
    float wcx = (float)(blockIdx.x * 16) + 7.5f;
    float wcy = (float)(blockIdx.y * 16) + 7.5f;

    const float* P = params + b * 13;

    // ---------------- phase 1a: cheap cull over all electrodes -----------
    bool surv = false;
    if (tid < NE) {
        float rho = P[0], lam = P[1];
        float a3 = P[6], a4 = P[7];
        float impx = P[8], impy = P[9], rot = P[10];
        float cr = __cosf(rot), sr = __sinf(rot);

        float exv = elec_x[tid] * cr - elec_y[tid] * sr + impx;
        float eyv = elec_x[tid] * sr + elec_y[tid] * cr + impy;
        float amp  = stim[(b * NE + tid) * 3 + 1];
        float pdur = stim[(b * NE + tid) * 3 + 2];

        if (amp > AMP_CUTOFF) {
            float cx = (exv / RET_PER_DVA - XRANGE0) / XYSTEP;
            float cy = (float)HH - (eyv / RET_PER_DVA - YRANGE0) / XYSTEP;
            float cy2 = 120.0f - cy;

            float rs = fmaxf(rho * amp * a3, 1.0f);
            float ls = lam * ex2_fast(a4 * (__log2f(pdur) - LOG2_045));
            ls = fminf(fmaxf(ls, 0.f), 0.99f);
            float t2 = sqrtf(1.0f - ls * ls);
            float sy = __fdividef(rs, TEMP1c * t2);       // max eigenvalue of cov
            float R2c = (CULL_T / HALF_LOG2E) * sy;       // CULL_T / lmin, exact

            float dx = fmaxf(fabsf(wcx - cx) - 7.5f, 0.f);
            float dy = fmaxf(fabsf(wcy - cy2) - 7.5f, 0.f);
            surv = (fmaf(dx, dx, dy * dy) <= R2c);
        }
    }

    // block-wide deterministic compaction (ascending e)
    unsigned mask = __ballot_sync(0xffffffffu, surv);
    if (lane == 0) wcnt[w] = __popc(mask);
    __syncthreads();
    int off = 0;
#pragma unroll
    for (int i = 0; i < 8; i++) off += (i < w) ? wcnt[i] : 0;
    if (tid == 0) {
        int tot = 0;
#pragma unroll
        for (int i = 0; i < 8; i++) tot += wcnt[i];
        s_len = tot;
    }
    if (surv) {
        int slot = off + __popc(mask & ((1u << lane) - 1u));
        cIdx[slot] = tid;
    }
    __syncthreads();
    int n = s_len;

    // ---------------- phase 1b: full chain for survivors only ------------
    if (tid < n) {
        int e = cIdx[tid];
        float rho = P[0], lam = P[1], osc = P[2];
        float a0 = P[3], a1 = P[4], a2 = P[5], a3 = P[6], a4 = P[7];
        float impx = P[8], impy = P[9], rot = P[10], lodx = P[11];
        float cr = __cosf(rot), sr = __sinf(rot);

        float exv = elec_x[e] * cr - elec_y[e] * sr + impx;
        float eyv = elec_x[e] * sr + elec_y[e] * cr + impy;
        float freq = stim[(b * NE + e) * 3 + 0];
        float amp  = stim[(b * NE + e) * 3 + 1];
        float pdur = stim[(b * NE + e) * 3 + 2];

        float offx = lodx - OD_OFF_Xc;
        float qx = (exv - offx - XLOWc) * (1.0f / STEP_Xc);
        float qy = (eyv - YLOWc) * (1.0f / STEP_Yc);

        float fx = fminf(fmaxf(floorf(qx), 0.f), (float)(N_INTERP - 2));
        float fy = fminf(fmaxf(floorf(qy), 0.f), (float)(N_INTERP - 2));
        int ix = (int)fx, iy = (int)fy;
        float ax = fminf(fmaxf(qx - fx, 0.f), 1.f);
        float ay = fminf(fmaxf(qy - fy, 0.f), 1.f);
        float g00 = slopes[iy * N_INTERP + ix];
        float g01 = slopes[iy * N_INTERP + ix + 1];
        float g10 = slopes[(iy + 1) * N_INTERP + ix];
        float g11 = slopes[(iy + 1) * N_INTERP + ix + 1];
        float top = g00 + ax * (g01 - g00);
        float bot = g10 + ax * (g11 - g10);
        float th = top + ay * (bot - top);
        if (th < -PIc * 0.5f) th += PIc;
        th *= osc;

        float rs = fmaxf(rho * amp * a3, 1.0f);
        float ls = lam * ex2_fast(a4 * (__log2f(pdur) - LOG2_045));
        ls = fminf(fmaxf(ls, 0.f), 0.99f);
        float bright = a0 * ex2_fast(a1 * __log2f(fmaxf(amp, 1e-5f))) + a2 * freq;

        float t2 = sqrtf(1.0f - ls * ls);
        float sy = __fdividef(rs, TEMP1c * t2);
        float sx = rs * t2 * (1.0f / TEMP1c);
        float s = __sinf(th), c = __cosf(th);
        float cov00 = sx * c * c + sy * s * s;
        float cov01 = (sx - sy) * s * c;
        float cov11 = sx * s * s + sy * c * c;
        float det = cov00 * cov11 - cov01 * cov01;
        float rdet = __fdividef(1.0f, det);
        float inv00 = cov11 * rdet;
        float inv01 = -cov01 * rdet;
        float inv11 = cov00 * rdet;

        float c00 = NEG_HALF_LOG2E * inv00;
        float c01 = 2.0f * NEG_HALF_LOG2E * inv01;
        float c11 = NEG_HALF_LOG2E * inv11;

        float cx = (exv / RET_PER_DVA - XRANGE0) / XYSTEP;
        float cy = (float)HH - (eyv / RET_PER_DVA - YRANGE0) / XYSTEP;
        float cy2 = 120.0f - cy;   // d1 = cy2 - r

        cA[tid] = make_float4(cx, cy2, 0.f, bright);
        cB[tid] = make_float4(c00, c01, c11, 2.0f * c11);
    } else if (tid < n + 8) {
        // zero pad: contributes bright=0 -> exactly 0, no NaN (t stays 0)
        cA[tid] = make_float4(0.f, 0.f, 0.f, 0.f);
        cB[tid] = make_float4(0.f, 0.f, 0.f, 0.f);
    }
    __syncthreads();

    // ---------------- phase 2: ILP-2 survivor loop (16x16, 8-row FD) -----
    int lx = lane & 15;
    int ly = lane >> 4;
    float cf  = (float)(blockIdx.x * 16 + lx);
    float rf0 = (float)(blockIdx.y * 16 + ly * 8);

    float acc[8];
#pragma unroll
    for (int i = 0; i < 8; i++) acc[i] = 0.f;

    for (int s = w; s < n; s += 16) {
        float4 SA0 = cA[s],     SB0 = cB[s];
        float4 SA1 = cA[s + 8], SB1 = cB[s + 8];   // pad makes this safe

        // chain 0
        float d0a = cf - SA0.x;
        float k1a = SB0.y * d0a;
        float k0a = (SB0.x * d0a) * d0a;
        float d1a = SA0.y - rf0;
        float ta   = fmaf(fmaf(SB0.z, d1a, k1a), d1a, k0a);
        float dlta = fmaf(SB0.z, fmaf(-2.0f, d1a, 1.0f), -k1a);

        // chain 1 (independent)
        float d0b = cf - SA1.x;
        float k1b = SB1.y * d0b;
        float k0b = (SB1.x * d0b) * d0b;
        float d1b = SA1.y - rf0;
        float tb   = fmaf(fmaf(SB1.z, d1b, k1b), d1b, k0b);
        float dltb = fmaf(SB1.z, fmaf(-2.0f, d1b, 1.0f), -k1b);

#pragma unroll
        for (int i = 0; i < 8; i++) {
            acc[i] = fmaf(SA0.w, ex2_fast(ta), acc[i]);
            acc[i] = fmaf(SA1.w, ex2_fast(tb), acc[i]);
            ta += dlta; dlta += SB0.w;             // 2*c11 (chain 0)
            tb += dltb; dltb += SB1.w;             // 2*c11 (chain 1)
        }
    }

    // partials: pixel index in tile = (ly*8 + i)*16 + lx
    int pbase = ly * 128 + lx;
#pragma unroll
    for (int i = 0; i < 8; i++)
        spart[w][pbase + i * 16] = acc[i];
    __syncthreads();

    // ---------------- phase 3: block-local reduction ---------------------
    {
        // fixed warp order -> deterministic fp sum
        float v = spart[0][tid] + spart[1][tid] + spart[2][tid] + spart[3][tid]
                + spart[4][tid] + spart[5][tid] + spart[6][tid] + spart[7][tid];
        int r  = blockIdx.y * 16 + (tid >> 4);
        int cc = blockIdx.x * 16 + (tid & 15);
        if (r < HH && cc < WW)
            out[b * NPIX + r * WW + cc] = v;
    }
}

extern "C" void kernel_launch(void* const* d_in, const int* in_sizes, int n_in,
                              void* d_out, int out_size) {
    const float* stim   = (const float*)d_in[0];  // (8,225,3)
    const float* params = (const float*)d_in[1];  // (8,13)
    const float* ex     = (const float*)d_in[2];  // (1,225)
    const float* ey     = (const float*)d_in[3];  // (1,225)
    const float* slopes = (const float*)d_in[4];  // (200,200)
    // d_in[5] = pixelgrid: implied analytically, unused

    dim3 grid(TILES_X, TILES_Y, NB);   // (8,8,8) = 512 blocks x 256 threads
    mvg_kernel<<<grid, 256>>>(stim, params, ex, ey, slopes, (float*)d_out);
}